// round 9
// baseline (speedup 1.0000x reference)
#include <cuda_runtime.h>
#include <cstdint>

// -------------------------------------------------------------------------
// SimpleESN persistent kernel, round 6.
//  - No global barrier: 16 per-slice monotonic counters; producers (8 CTAs
//    per slice) release-add after storing h, consumer warps acquire-poll.
//    3-way h buffering makes this gate WAR-safe. Replay-safe via ticket.
//  - Sparse input projection: per-column nonzero lists (~0.6 avg), x loads
//    prefetched at step top.
//  - k-loop: warp-private triple-buffered smem staging (syncwarp only),
//    bank-row-aligned chunk layout (1 wavefront per h LDS.128).
// -------------------------------------------------------------------------

namespace {
constexpr int B_      = 16;
constexpr int T_      = 2048;
constexpr int F_      = 128;
constexpr int U_      = 2048;
constexpr int GRID    = 128;
constexpr int THREADS = 512;
constexpr int COLS    = 16;
constexpr int NCHUNK  = 8;            // 8 chunks x 16 k per warp slice
constexpr int CHF     = 256;          // floats per chunk (16 k x 16 b)
constexpr int SLICE   = 2048;         // floats per warp slice (128 k x 16 b)
constexpr int BST     = 20;
constexpr int REDW    = COLS * BST;   // 320
constexpr int NZCAP   = 16;           // max tracked nonzeros per column
}

// h triple buffer; within slice: [chunk8][ic4][row2][g8][4]
__device__ __align__(16) float g_h[3][U_ * B_];
__device__ unsigned g_cnt[16 * 32];   // slice counters, 128B apart
__device__ unsigned g_ticket = 0;

struct SmemLayout {
  float Ws[U_ * COLS];       // 131072 B  [k][c]
  float sbuf[16][3][CHF];    //  49152 B  warp-private staging rings
  float red[16 * REDW];      //  20480 B
  float nzw[COLS][NZCAP];    //   1024 B
  int   nzf[COLS][NZCAP];    //   1024 B
  int   nzc[COLS];
  float bias_s[COLS];
  float wout_s[COLS];
  float ybuf[COLS * B_];
  unsigned base;
};
static_assert(sizeof(SmemLayout) <= 227 * 1024, "smem");

using u64 = unsigned long long;

__device__ __forceinline__ unsigned ld_acq(unsigned* p) {
  unsigned v;
  asm volatile("ld.acquire.gpu.global.u32 %0, [%1];" : "=r"(v) : "l"(p) : "memory");
  return v;
}
__device__ __forceinline__ void red_rel_add(unsigned* p) {
  asm volatile("red.release.gpu.global.add.u32 [%0], 1;" :: "l"(p) : "memory");
}
__device__ __forceinline__ float4 ldcg4(const float* p) {
  float4 v;
  asm volatile("ld.global.cg.v4.f32 {%0,%1,%2,%3}, [%4];"
               : "=f"(v.x), "=f"(v.y), "=f"(v.z), "=f"(v.w) : "l"(p));
  return v;
}
__device__ __forceinline__ u64 splat2(float w) {
  u64 r;
  asm("mov.b64 %0, {%1, %1};" : "=l"(r) : "r"(__float_as_uint(w)));
  return r;
}
__device__ __forceinline__ void fmax2(u64& a, u64 h, u64 w) {
  asm("fma.rn.f32x2 %0, %1, %2, %0;" : "+l"(a) : "l"(h), "l"(w));
}
__device__ __forceinline__ u64 addx2(u64 a, u64 b) {
  u64 r;
  asm("add.rn.f32x2 %0, %1, %2;" : "=l"(r) : "l"(a), "l"(b));
  return r;
}

__global__ void __launch_bounds__(THREADS, 1) esn_kernel(
    const float* __restrict__ x,     // [B,T,F]
    const float* __restrict__ kern,  // [F,U]
    const float* __restrict__ W,     // [U,U]
    const float* __restrict__ bias,  // [U]
    const float* __restrict__ wout,  // [U,1]
    const float* __restrict__ bout,  // [1]
    float* __restrict__ out)         // [B,1]
{
  extern __shared__ unsigned char smem_raw[];
  SmemLayout& s = *reinterpret_cast<SmemLayout*>(smem_raw);
  const int tid  = threadIdx.x;
  const int n0   = blockIdx.x * COLS;
  const int lane = tid & 31;
  const int wrp  = tid >> 5;          // 0..15 = consumed slice id
  const int kk   = lane >> 3;         // k within warp group (0..3)
  const int hf   = (lane >> 2) & 1;   // batch half
  const int q    = lane & 3;          // col quad
  const int cS   = (tid >> 4) & 15;   // output col (tid<256)
  const int bS   = tid & 15;          // output batch

  if (blockIdx.x == 0 && tid < B_) out[tid] = bout[0];

  // ---- replay-safe round base ----
  if (tid == 0) {
    unsigned tk = atomicAdd(&g_ticket, 1u);
    s.base = (tk / (unsigned)GRID) * (8u * (unsigned)T_);
  }

  // ---- persistent smem: W slice ----
  for (int i = tid; i < U_ * COLS; i += THREADS) {
    int k = i >> 4, c = i & 15;
    s.Ws[i] = W[k * U_ + n0 + c];
  }
  if (tid < COLS) {
    s.bias_s[tid] = bias[n0 + tid];
    s.wout_s[tid] = wout[n0 + tid];
  }

  // ---- sparse input-kernel lists: warp w scans column w ----
  if (wrp < COLS) {
    const int c = wrp;
    int cnt = 0;
    #pragma unroll
    for (int r = 0; r < 4; ++r) {
      int f = r * 32 + lane;
      float wv = kern[f * U_ + n0 + c];
      unsigned m = __ballot_sync(0xFFFFFFFFu, wv != 0.f);
      if (wv != 0.f) {
        int pos = cnt + __popc(m & ((1u << lane) - 1u));
        if (pos < NZCAP) { s.nzw[c][pos] = wv; s.nzf[c][pos] = f; }
      }
      cnt += __popc(m);
    }
    if (lane == 0) s.nzc[c] = cnt < NZCAP ? cnt : NZCAP;
    if (lane < NZCAP && lane >= cnt) { s.nzw[c][lane] = 0.f; s.nzf[c][lane] = 0; }
  }
  __syncthreads();

  const unsigned base = s.base;

  // producer store index (permuted chunk layout), constant over t
  int pidx = 0, cntc = 0, fl[8];
  if (tid < 256) {
    const int n = n0 + cS;
    pidx = (n >> 7) * SLICE + ((n >> 4) & 7) * CHF + ((n >> 2) & 3) * 64 +
           ((bS >> 2) & 1) * 32 + ((n & 3) * 2 + (bS >> 3)) * 4 + (bS & 3);
    cntc = s.nzc[cS];
    #pragma unroll
    for (int i = 0; i < 8; ++i) fl[i] = s.nzf[cS][i];
  }

  // consumer constants
  float* const myring = &s.sbuf[wrp][0][0];
  const int hoffB = (kk * 2 + hf) * 4;  // within-chunk float offset
  const float* const wbase = &s.Ws[(wrp * 128 + kk) * COLS + q * 4];
  unsigned* const mycnt = &g_cnt[wrp * 32];
  unsigned* const prodcnt = &g_cnt[(blockIdx.x >> 3) * 32];

  float hval = 0.f;
  int bw = 0, br = 2;  // write buf t%3, read buf (t-1)%3

  for (int t = 0; t < T_; ++t) {
    // ---- prefetch sparse-u x values (independent of h) ----
    float xv[8];
    if (tid < 256) {
      const float* xb = x + bS * (T_ * F_) + t * F_;
      #pragma unroll
      for (int i = 0; i < 8; ++i) xv[i] = __ldg(xb + fl[i]);
    }

    float dot = 0.f;
    if (t > 0) {
      // ---- wait for this warp's slice of h[t-1] ----
      const unsigned tgt = base + 8u * (unsigned)t;
      while ((int)(ld_acq(mycnt) - tgt) < 0) {}

      const float* hsl = g_h[br] + wrp * SLICE;

      u64 acc[16];
      #pragma unroll
      for (int j = 0; j < 16; ++j) acc[j] = 0ull;

      float4 cur0 = ldcg4(hsl + lane * 4);
      float4 cur1 = ldcg4(hsl + (lane + 32) * 4);
      float4 nxt0 = ldcg4(hsl + CHF + lane * 4);
      float4 nxt1 = ldcg4(hsl + CHF + (lane + 32) * 4);

      #pragma unroll
      for (int c = 0; c < NCHUNK; ++c) {
        float* buf = myring + (c % 3) * CHF;
        *reinterpret_cast<float4*>(buf + lane * 4) = cur0;
        *reinterpret_cast<float4*>(buf + (lane + 32) * 4) = cur1;

        float4 pre0, pre1;
        if (c + 2 < NCHUNK) {
          const float* p = hsl + (c + 2) * CHF;
          pre0 = ldcg4(p + lane * 4);
          pre1 = ldcg4(p + (lane + 32) * 4);
        }
        __syncwarp();

        const float* hb = buf + hoffB;
        const float* wc = wbase + c * (16 * COLS);
        #pragma unroll
        for (int ic = 0; ic < 4; ++ic) {
          ulonglong2 ha  = *reinterpret_cast<const ulonglong2*>(hb + ic * 64);
          ulonglong2 hb2 = *reinterpret_cast<const ulonglong2*>(hb + ic * 64 + 32);
          const float4 wv = *reinterpret_cast<const float4*>(wc + ic * (4 * COLS));
          u64 w0 = splat2(wv.x), w1 = splat2(wv.y);
          u64 w2 = splat2(wv.z), w3 = splat2(wv.w);
          fmax2(acc[0],  ha.x,  w0); fmax2(acc[1],  ha.y,  w0);
          fmax2(acc[2],  hb2.x, w0); fmax2(acc[3],  hb2.y, w0);
          fmax2(acc[4],  ha.x,  w1); fmax2(acc[5],  ha.y,  w1);
          fmax2(acc[6],  hb2.x, w1); fmax2(acc[7],  hb2.y, w1);
          fmax2(acc[8],  ha.x,  w2); fmax2(acc[9],  ha.y,  w2);
          fmax2(acc[10], hb2.x, w2); fmax2(acc[11], hb2.y, w2);
          fmax2(acc[12], ha.x,  w3); fmax2(acc[13], ha.y,  w3);
          fmax2(acc[14], hb2.x, w3); fmax2(acc[15], hb2.y, w3);
        }
        cur0 = nxt0; cur1 = nxt1;
        if (c + 2 < NCHUNK) { nxt0 = pre0; nxt1 = pre1; }
      }

      // reduce over kk (lane bits 3,4); keeps (hf, q)
      #pragma unroll
      for (int j = 0; j < 16; ++j) {
        acc[j] = addx2(acc[j], __shfl_xor_sync(0xFFFFFFFFu, acc[j], 8));
        acc[j] = addx2(acc[j], __shfl_xor_sync(0xFFFFFFFFu, acc[j], 16));
      }
      if (kk == 0) {
        #pragma unroll
        for (int c = 0; c < 4; ++c) {
          float* r = &s.red[wrp * REDW + (4 * q + c) * BST + hf * 8];
          *reinterpret_cast<ulonglong2*>(r) =
              make_ulonglong2(acc[c * 4 + 0], acc[c * 4 + 1]);
          *reinterpret_cast<ulonglong2*>(r + 4) =
              make_ulonglong2(acc[c * 4 + 2], acc[c * 4 + 3]);
        }
      }
      __syncthreads();

      if (tid < 256) {
        float sum = 0.f;
        const float* rp = &s.red[cS * BST + bS];
        #pragma unroll
        for (int g = 0; g < 16; ++g) sum += rp[g * REDW];
        dot = sum;
      }
    }

    // ---- u + tanh + store h ----
    if (tid < 256) {
      float u = s.bias_s[cS];
      #pragma unroll
      for (int i = 0; i < 8; ++i) u += xv[i] * s.nzw[cS][i];
      for (int i = 8; i < cntc; ++i)  // astronomically rare tail
        u += __ldg(&x[bS * (T_ * F_) + t * F_ + s.nzf[cS][i]]) * s.nzw[cS][i];
      hval = tanhf(u + dot);
      g_h[bw][pidx] = hval;
    }
    __syncthreads();  // h stores + red reads complete
    if (tid == 0) red_rel_add(prodcnt);

    br = bw;
    bw = (bw == 2) ? 0 : bw + 1;
  }

  // ---- readout ----
  if (tid < 256) s.ybuf[cS * B_ + bS] = hval * s.wout_s[cS];
  __syncthreads();
  if (tid < B_) {
    float y = 0.f;
    #pragma unroll
    for (int c = 0; c < COLS; ++c) y += s.ybuf[c * B_ + tid];
    atomicAdd(&out[tid], y);
  }
}

extern "C" void kernel_launch(void* const* d_in, const int* in_sizes, int n_in,
                              void* d_out, int out_size) {
  (void)in_sizes; (void)n_in; (void)out_size;
  const float* x    = (const float*)d_in[0];
  const float* kern = (const float*)d_in[1];
  const float* W    = (const float*)d_in[2];
  const float* bias = (const float*)d_in[3];
  const float* wout = (const float*)d_in[4];
  const float* bout = (const float*)d_in[5];

  cudaFuncSetAttribute(esn_kernel, cudaFuncAttributeMaxDynamicSharedMemorySize,
                       (int)sizeof(SmemLayout));
  esn_kernel<<<GRID, THREADS, sizeof(SmemLayout)>>>(
      x, kern, W, bias, wout, bout, (float*)d_out);
}

// round 10
// speedup vs baseline: 1.1946x; 1.1946x over previous
#include <cuda_runtime.h>
#include <cstdint>

// -------------------------------------------------------------------------
// SimpleESN, round 9.
//  - Input projection fully precomputed into g_u[t][n][b] (256MB __device__)
//    by two setup kernels (nz scan + per-t transpose&project). Hot loop's
//    u = ONE coalesced LDG.32 per thread.
//  - h staging via cp.async.cg (4-slot ring, distance-3): no LDG->reg->STS
//    round trip, no L1 pollution, fewer registers.
//  - Dataflow sync (16 per-slice counters, release/acquire), 3-way h buffer.
// -------------------------------------------------------------------------

namespace {
constexpr int B_      = 16;
constexpr int T_      = 2048;
constexpr int F_      = 128;
constexpr int U_      = 2048;
constexpr int GRID    = 128;
constexpr int THREADS = 512;
constexpr int COLS    = 16;
constexpr int NCHUNK  = 8;            // 8 chunks x 16 k per warp slice
constexpr int CHF     = 256;          // floats per chunk (16 k x 16 b)
constexpr int SLICE   = 2048;         // floats per warp slice
constexpr int BST     = 20;
constexpr int REDW    = COLS * BST;   // 320
constexpr int NZCAP   = 16;
}

// big scratch: precomputed input projection [t][n][b]
__device__ float g_u[T_ * U_ * B_];
// h triple buffer; within slice: [chunk8][ic4][row2][g8][4]
__device__ __align__(16) float g_h[3][U_ * B_];
__device__ unsigned g_cnt[16 * 32];   // slice counters, 128B apart
__device__ unsigned g_ticket = 0;
// nonzero lists of input kernel columns
__device__ int   g_nzc[U_];
__device__ int   g_nzf[U_ * NZCAP];
__device__ float g_nzw[U_ * NZCAP];

struct SmemLayout {
  float Ws[U_ * COLS];       // 131072 B  [k][c]
  float sbuf[16][4][CHF];    //  65536 B  warp-private cp.async rings
  float red[16 * REDW];      //  20480 B
  float wout_s[COLS];
  float ybuf[COLS * B_];
  unsigned base;
};
static_assert(sizeof(SmemLayout) <= 227 * 1024, "smem");

using u64 = unsigned long long;

__device__ __forceinline__ unsigned ld_acq(unsigned* p) {
  unsigned v;
  asm volatile("ld.acquire.gpu.global.u32 %0, [%1];" : "=r"(v) : "l"(p) : "memory");
  return v;
}
__device__ __forceinline__ void red_rel_add(unsigned* p) {
  asm volatile("red.release.gpu.global.add.u32 [%0], 1;" :: "l"(p) : "memory");
}
__device__ __forceinline__ void cpa16(uint32_t dst, const float* src) {
  asm volatile("cp.async.cg.shared.global [%0], [%1], 16;"
               :: "r"(dst), "l"(src) : "memory");
}
__device__ __forceinline__ u64 splat2(float w) {
  u64 r;
  asm("mov.b64 %0, {%1, %1};" : "=l"(r) : "r"(__float_as_uint(w)));
  return r;
}
__device__ __forceinline__ void fmax2(u64& a, u64 h, u64 w) {
  asm("fma.rn.f32x2 %0, %1, %2, %0;" : "+l"(a) : "l"(h), "l"(w));
}
__device__ __forceinline__ u64 addx2(u64 a, u64 b) {
  u64 r;
  asm("add.rn.f32x2 %0, %1, %2;" : "=l"(r) : "l"(a), "l"(b));
  return r;
}

// ---- setup kernel 1: nonzero lists per input-kernel column ----
__global__ void nz_kernel(const float* __restrict__ kern) {
  int n = blockIdx.x * blockDim.x + threadIdx.x;
  if (n >= U_) return;
  int cnt = 0;
  for (int f = 0; f < F_; ++f) {
    float v = kern[f * U_ + n];
    if (v != 0.f) {
      if (cnt < NZCAP) { g_nzw[n * NZCAP + cnt] = v; g_nzf[n * NZCAP + cnt] = f; }
      ++cnt;
    }
  }
  g_nzc[n] = cnt;
}

// ---- setup kernel 2: u[t][n][b] = bias[n] + sum_nz x[b][t][f]*w ----
__global__ void __launch_bounds__(512) uproj_kernel(
    const float* __restrict__ x, const float* __restrict__ kern,
    const float* __restrict__ bias) {
  __shared__ float sx[F_ * 20];  // [f][b], stride 20 (float4-aligned)
  const int t = blockIdx.x;
  for (int i = threadIdx.x; i < B_ * F_; i += blockDim.x) {
    int b = i >> 7, f = i & 127;
    sx[f * 20 + b] = x[(b * T_ + t) * F_ + f];
  }
  __syncthreads();
  for (int it = threadIdx.x; it < U_ * 4; it += blockDim.x) {
    int n = it >> 2, bq = it & 3;
    float bs = bias[n];
    float4 acc = make_float4(bs, bs, bs, bs);
    int cnt = g_nzc[n];
    if (cnt <= NZCAP) {
      for (int i2 = 0; i2 < cnt; ++i2) {
        int f = g_nzf[n * NZCAP + i2];
        float w = g_nzw[n * NZCAP + i2];
        float4 xv = *reinterpret_cast<const float4*>(&sx[f * 20 + bq * 4]);
        acc.x += xv.x * w; acc.y += xv.y * w;
        acc.z += xv.z * w; acc.w += xv.w * w;
      }
    } else {  // pathological dense fallback
      for (int f = 0; f < F_; ++f) {
        float w = kern[f * U_ + n];
        float4 xv = *reinterpret_cast<const float4*>(&sx[f * 20 + bq * 4]);
        acc.x += xv.x * w; acc.y += xv.y * w;
        acc.z += xv.z * w; acc.w += xv.w * w;
      }
    }
    *reinterpret_cast<float4*>(&g_u[t * (U_ * B_) + n * B_ + bq * 4]) = acc;
  }
}

// ---- main persistent kernel ----
__global__ void __launch_bounds__(THREADS, 1) esn_kernel(
    const float* __restrict__ W,     // [U,U]
    const float* __restrict__ wout,  // [U,1]
    const float* __restrict__ bout,  // [1]
    float* __restrict__ out)         // [B,1]
{
  extern __shared__ unsigned char smem_raw[];
  SmemLayout& s = *reinterpret_cast<SmemLayout*>(smem_raw);
  const int tid  = threadIdx.x;
  const int n0   = blockIdx.x * COLS;
  const int lane = tid & 31;
  const int wrp  = tid >> 5;          // 0..15 = consumed slice id
  const int kk   = lane >> 3;
  const int hf   = (lane >> 2) & 1;
  const int q    = lane & 3;
  const int cS   = (tid >> 4) & 15;   // output col (tid<256)
  const int bS   = tid & 15;          // output batch

  if (blockIdx.x == 0 && tid < B_) out[tid] = bout[0];

  if (tid == 0) {
    unsigned tk = atomicAdd(&g_ticket, 1u);
    s.base = (tk / (unsigned)GRID) * (8u * (unsigned)T_);
  }

  for (int i = tid; i < U_ * COLS; i += THREADS) {
    int k = i >> 4, c = i & 15;
    s.Ws[i] = W[k * U_ + n0 + c];
  }
  if (tid < COLS) s.wout_s[tid] = wout[n0 + tid];
  __syncthreads();

  const unsigned base = s.base;

  // producer store index (permuted chunk layout), constant over t
  int pidx = 0;
  if (tid < 256) {
    const int n = n0 + cS;
    pidx = (n >> 7) * SLICE + ((n >> 4) & 7) * CHF + ((n >> 2) & 3) * 64 +
           ((bS >> 2) & 1) * 32 + ((n & 3) * 2 + (bS >> 3)) * 4 + (bS & 3);
  }
  const float* uptr = g_u + (n0 + cS) * B_ + bS;  // advance by U_*B_ per t

  // consumer constants
  float* const myring = &s.sbuf[wrp][0][0];
  const uint32_t rbase = (uint32_t)__cvta_generic_to_shared(myring);
  const int hoffB = (kk * 2 + hf) * 4;
  const float* const wbase = &s.Ws[(wrp * 128 + kk) * COLS + q * 4];
  unsigned* const mycnt = &g_cnt[wrp * 32];
  unsigned* const prodcnt = &g_cnt[(blockIdx.x >> 3) * 32];

  float hval = 0.f;
  int bw = 0, br = 2;  // write buf, read buf

  for (int t = 0; t < T_; ++t) {
    // ---- u: one coalesced load, independent of h ----
    float uval = 0.f;
    if (tid < 256) uval = __ldg(uptr + t * (U_ * B_));

    float dot = 0.f;
    if (t > 0) {
      const unsigned tgt = base + 8u * (unsigned)t;
      while ((int)(ld_acq(mycnt) - tgt) < 0) {}

      const float* hsl = g_h[br] + wrp * SLICE;

      // prologue: chunks 0..2 into ring slots 0..2
      #pragma unroll
      for (int p = 0; p < 3; ++p) {
        uint32_t d = rbase + (unsigned)(p * CHF + lane * 4) * 4u;
        cpa16(d, hsl + p * CHF + lane * 4);
        cpa16(d + 512, hsl + p * CHF + (lane + 32) * 4);
        asm volatile("cp.async.commit_group;" ::: "memory");
      }

      u64 acc[16];
      #pragma unroll
      for (int j = 0; j < 16; ++j) acc[j] = 0ull;

      #pragma unroll
      for (int c = 0; c < NCHUNK; ++c) {
        // issue chunk c+3 (slot safe: held chunk c-1, already consumed)
        if (c + 3 < NCHUNK) {
          uint32_t d = rbase + (unsigned)(((c + 3) & 3) * CHF + lane * 4) * 4u;
          cpa16(d, hsl + (c + 3) * CHF + lane * 4);
          cpa16(d + 512, hsl + (c + 3) * CHF + (lane + 32) * 4);
          asm volatile("cp.async.commit_group;" ::: "memory");
        }
        // wait for chunk c:  allowed pending = min(3, 7-c)
        const int wn = (NCHUNK - 1 - c) < 3 ? (NCHUNK - 1 - c) : 3;
        if (wn == 3)      asm volatile("cp.async.wait_group 3;" ::: "memory");
        else if (wn == 2) asm volatile("cp.async.wait_group 2;" ::: "memory");
        else if (wn == 1) asm volatile("cp.async.wait_group 1;" ::: "memory");
        else              asm volatile("cp.async.wait_group 0;" ::: "memory");
        __syncwarp();

        const float* hb = myring + (c & 3) * CHF + hoffB;
        const float* wc = wbase + c * (16 * COLS);
        #pragma unroll
        for (int ic = 0; ic < 4; ++ic) {
          ulonglong2 ha  = *reinterpret_cast<const ulonglong2*>(hb + ic * 64);
          ulonglong2 hb2 = *reinterpret_cast<const ulonglong2*>(hb + ic * 64 + 32);
          const float4 wv = *reinterpret_cast<const float4*>(wc + ic * (4 * COLS));
          u64 w0 = splat2(wv.x), w1 = splat2(wv.y);
          u64 w2 = splat2(wv.z), w3 = splat2(wv.w);
          fmax2(acc[0],  ha.x,  w0); fmax2(acc[1],  ha.y,  w0);
          fmax2(acc[2],  hb2.x, w0); fmax2(acc[3],  hb2.y, w0);
          fmax2(acc[4],  ha.x,  w1); fmax2(acc[5],  ha.y,  w1);
          fmax2(acc[6],  hb2.x, w1); fmax2(acc[7],  hb2.y, w1);
          fmax2(acc[8],  ha.x,  w2); fmax2(acc[9],  ha.y,  w2);
          fmax2(acc[10], hb2.x, w2); fmax2(acc[11], hb2.y, w2);
          fmax2(acc[12], ha.x,  w3); fmax2(acc[13], ha.y,  w3);
          fmax2(acc[14], hb2.x, w3); fmax2(acc[15], hb2.y, w3);
        }
        __syncwarp();  // all lanes done with slot before reuse
      }

      // reduce over kk (lane bits 3,4); keeps (hf, q)
      #pragma unroll
      for (int j = 0; j < 16; ++j) {
        acc[j] = addx2(acc[j], __shfl_xor_sync(0xFFFFFFFFu, acc[j], 8));
        acc[j] = addx2(acc[j], __shfl_xor_sync(0xFFFFFFFFu, acc[j], 16));
      }
      if (kk == 0) {
        #pragma unroll
        for (int c = 0; c < 4; ++c) {
          float* r = &s.red[wrp * REDW + (4 * q + c) * BST + hf * 8];
          *reinterpret_cast<ulonglong2*>(r) =
              make_ulonglong2(acc[c * 4 + 0], acc[c * 4 + 1]);
          *reinterpret_cast<ulonglong2*>(r + 4) =
              make_ulonglong2(acc[c * 4 + 2], acc[c * 4 + 3]);
        }
      }
      __syncthreads();

      if (tid < 256) {
        float sum = 0.f;
        const float* rp = &s.red[cS * BST + bS];
        #pragma unroll
        for (int g = 0; g < 16; ++g) sum += rp[g * REDW];
        dot = sum;
      }
    }

    // ---- tanh + store h ----
    if (tid < 256) {
      hval = tanhf(uval + dot);
      g_h[bw][pidx] = hval;
    }
    __syncthreads();
    if (tid == 0) red_rel_add(prodcnt);

    br = bw;
    bw = (bw == 2) ? 0 : bw + 1;
  }

  // ---- readout ----
  if (tid < 256) s.ybuf[cS * B_ + bS] = hval * s.wout_s[cS];
  __syncthreads();
  if (tid < B_) {
    float y = 0.f;
    #pragma unroll
    for (int c = 0; c < COLS; ++c) y += s.ybuf[c * B_ + tid];
    atomicAdd(&out[tid], y);
  }
}

extern "C" void kernel_launch(void* const* d_in, const int* in_sizes, int n_in,
                              void* d_out, int out_size) {
  (void)in_sizes; (void)n_in; (void)out_size;
  const float* x    = (const float*)d_in[0];
  const float* kern = (const float*)d_in[1];
  const float* W    = (const float*)d_in[2];
  const float* bias = (const float*)d_in[3];
  const float* wout = (const float*)d_in[4];
  const float* bout = (const float*)d_in[5];

  nz_kernel<<<(U_ + 255) / 256, 256>>>(kern);
  uproj_kernel<<<T_, 512>>>(x, kern, bias);

  cudaFuncSetAttribute(esn_kernel, cudaFuncAttributeMaxDynamicSharedMemorySize,
                       (int)sizeof(SmemLayout));
  esn_kernel<<<GRID, THREADS, sizeof(SmemLayout)>>>(
      W, wout, bout, (float*)d_out);
}